// round 6
// baseline (speedup 1.0000x reference)
#include <cuda_runtime.h>
#include <cuda_bf16.h>
#include <cuda_fp16.h>
#include <cstdint>

// Problem constants (fixed shapes for SoftPhongShaderShadow_36197984371119)
#define PN   8
#define PH   512
#define PW   512
#define PK   4
#define NPIX (PN * PH * PW)        // 2,097,152
#define HW_SHIFT 18                // H*W = 262144 = 2^18
#define PF   100000                // faces
#define PV   50000                 // verts

#define SIGMA_     1.0e-4f
#define GAMMA_     1.0e-4f
#define ZNEAR_     1.0f
#define ZFAR_      100.0f
#define EPS_BLEND_ 1e-10f
#define INV_SIGMA  (1.0f / SIGMA_)
#define INV_GAMMA  (1.0f / GAMMA_)
#define INV_ZRANGE (1.0f / (ZFAR_ - ZNEAR_))

struct F3 { float x, y, z; };

__device__ __forceinline__ F3 ldg3(const float* __restrict__ p) {
    F3 r; r.x = __ldg(p); r.y = __ldg(p + 1); r.z = __ldg(p + 2); return r;
}
__device__ __forceinline__ float dot3(F3 a, F3 b) {
    return fmaf(a.x, b.x, fmaf(a.y, b.y, a.z * b.z));
}

// Packed per-face record in a 32B slot (2 x uint4):
//  q0 (8 halves):  v0x v0y v0z v1x v1y v1z v2x v2y
//  q1.x (half2):   v2z, 0
//  q1.y:           n0 packed 10-10-10
//  q1.z:           n1 packed 10-10-10
//  q1.w:           n2 packed 10-10-10
// -> 2 x LDG.128 per fragment, 1 L2 sector pair, never crosses a 128B line.
__device__ uint4 g_face_rec[PF * 2];

__device__ __forceinline__ uint32_t pack_h2(float a, float b) {
    __half2 h = __halves2half2(__float2half_rn(a), __float2half_rn(b));
    return *reinterpret_cast<uint32_t*>(&h);
}
__device__ __forceinline__ float2 unp_h2(uint32_t u) {
    return __half22float2(*reinterpret_cast<__half2*>(&u));
}

// quantize unit-vector component x in [-1,1] to 10 bits
__device__ __forceinline__ uint32_t q10(float x) {
    float t = fminf(fmaxf(fmaf(x, 511.5f, 511.5f), 0.0f), 1023.0f);
    return (uint32_t)__float2int_rn(t);
}
__device__ __forceinline__ uint32_t packn(F3 n) {
    return q10(n.x) | (q10(n.y) << 10) | (q10(n.z) << 20);
}
#define DEQ10 (1.0f / 511.5f)
__device__ __forceinline__ F3 unpackn(uint32_t u) {
    F3 r;
    r.x = fmaf((float)(u & 1023u),         DEQ10, -1.0f);
    r.y = fmaf((float)((u >> 10) & 1023u), DEQ10, -1.0f);
    r.z = fmaf((float)((u >> 20) & 1023u), DEQ10, -1.0f);
    return r;
}

__global__ void __launch_bounds__(256)
build_face_records(const int*   __restrict__ faces,
                   const float* __restrict__ verts,
                   const float* __restrict__ vnormals)
{
    const int f = blockIdx.x * blockDim.x + threadIdx.x;
    if (f >= PF) return;
    const int i0 = __ldg(faces + 3 * f + 0);
    const int i1 = __ldg(faces + 3 * f + 1);
    const int i2 = __ldg(faces + 3 * f + 2);
    const F3 v0 = ldg3(verts + 3 * i0);
    const F3 v1 = ldg3(verts + 3 * i1);
    const F3 v2 = ldg3(verts + 3 * i2);
    const F3 n0 = ldg3(vnormals + 3 * i0);
    const F3 n1 = ldg3(vnormals + 3 * i1);
    const F3 n2 = ldg3(vnormals + 3 * i2);
    uint4 q0, q1;
    q0.x = pack_h2(v0.x, v0.y);
    q0.y = pack_h2(v0.z, v1.x);
    q0.z = pack_h2(v1.y, v1.z);
    q0.w = pack_h2(v2.x, v2.y);
    q1.x = pack_h2(v2.z, 0.0f);
    q1.y = packn(n0);
    q1.z = packn(n1);
    q1.w = packn(n2);
    uint4* r = g_face_rec + (size_t)f * 2;
    r[0] = q0;
    r[1] = q1;
}

__global__ void __launch_bounds__(256)
soft_phong_kernel(
    const float* __restrict__ bary,            // (N,H,W,K,3)
    const float* __restrict__ zbuf,            // (N,H,W,K)
    const float* __restrict__ dists,           // (N,H,W,K)
    const float* __restrict__ texels,          // (N,H,W,K,3)
    const float* __restrict__ vis_maps,        // (N,H,W,3)
    const float* __restrict__ light_location,  // (N,3)
    const float* __restrict__ light_ambient,   // (N,3)
    const float* __restrict__ light_diffuse,   // (N,3)
    const float* __restrict__ light_specular,  // (N,3)
    const float* __restrict__ camera_center,   // (N,3)
    const float* __restrict__ mat_ambient,     // (N,3)
    const float* __restrict__ mat_diffuse,     // (N,3)
    const float* __restrict__ mat_specular,    // (N,3)
    const float* __restrict__ shininess,       // (N,)
    const int*   __restrict__ pix_to_face,     // (N,H,W,K)
    float*       __restrict__ out)             // (N,H,W,4)
{
    const int tid = blockIdx.x * blockDim.x + threadIdx.x;
    if (tid >= NPIX) return;
    const int n = tid >> HW_SHIFT;

    // ---- streaming per-pixel loads (vectorized, streaming cache hint) ----
    const int4   p2f = __ldcs((const int4*)pix_to_face + tid);
    const float4 zb  = __ldcs((const float4*)zbuf + tid);
    const float4 ds  = __ldcs((const float4*)dists + tid);

    const float4* bp = (const float4*)(bary + (size_t)tid * 12);
    const float4 bv0 = __ldcs(bp + 0);
    const float4 bv1 = __ldcs(bp + 1);
    const float4 bv2 = __ldcs(bp + 2);

    const float4* tp = (const float4*)(texels + (size_t)tid * 12);
    const float4 tv0 = __ldcs(tp + 0);
    const float4 tv1 = __ldcs(tp + 1);
    const float4 tv2 = __ldcs(tp + 2);

    F3 vis;
    {
        const float* vp = vis_maps + (size_t)tid * 3;
        vis.x = __ldcs(vp); vis.y = __ldcs(vp + 1); vis.z = __ldcs(vp + 2);
    }

    // ---- per-batch constants (uniform per block -> L1 broadcast) ----
    const F3 Lloc = ldg3(light_location + 3 * n);
    const F3 Cam  = ldg3(camera_center + 3 * n);
    const F3 lamb = ldg3(light_ambient + 3 * n);
    const F3 ldif = ldg3(light_diffuse + 3 * n);
    const F3 lspc = ldg3(light_specular + 3 * n);
    const F3 mamb = ldg3(mat_ambient + 3 * n);
    const F3 mdif = ldg3(mat_diffuse + 3 * n);
    const F3 mspc = ldg3(mat_specular + 3 * n);
    const float sh = __ldg(shininess + n);

    // precombined coefficients
    const F3 amb  = { mamb.x * lamb.x, mamb.y * lamb.y, mamb.z * lamb.z };
    const F3 ks   = { mspc.x * lspc.x, mspc.y * lspc.y, mspc.z * lspc.z };
    const F3 kdv  = { mdif.x * ldif.x * vis.x,
                      mdif.y * ldif.y * vis.y,
                      mdif.z * ldif.z * vis.z };

    const int   fidx[PK] = { p2f.x, p2f.y, p2f.z, p2f.w };
    const float zbk[PK]  = { zb.x, zb.y, zb.z, zb.w };
    const float dsk[PK]  = { ds.x, ds.y, ds.z, ds.w };
    const float bk[PK][3] = {
        { bv0.x, bv0.y, bv0.z }, { bv0.w, bv1.x, bv1.y },
        { bv1.z, bv1.w, bv2.x }, { bv2.y, bv2.z, bv2.w } };
    const float tk[PK][3] = {
        { tv0.x, tv0.y, tv0.z }, { tv0.w, tv1.x, tv1.y },
        { tv1.z, tv1.w, tv2.x }, { tv2.y, tv2.z, tv2.w } };

    float prob[PK], zinv[PK];
    F3 col[PK];

    #pragma unroll
    for (int k = 0; k < PK; k++) {
        const int f = fidx[k];
        if (f >= 0) {
            // gather packed face record: 2 x LDG.128
            const uint4* fr = g_face_rec + (size_t)f * 2;
            const uint4 q0 = __ldg(fr + 0);
            const uint4 q1 = __ldg(fr + 1);

            const float2 a0 = unp_h2(q0.x);  // v0x v0y
            const float2 a1 = unp_h2(q0.y);  // v0z v1x
            const float2 a2 = unp_h2(q0.z);  // v1y v1z
            const float2 a3 = unp_h2(q0.w);  // v2x v2y
            const float2 a4 = unp_h2(q1.x);  // v2z --

            const F3 va = { a0.x, a0.y, a1.x };
            const F3 vb = { a1.y, a2.x, a2.y };
            const F3 vc = { a3.x, a3.y, a4.x };
            const F3 na = unpackn(q1.y);
            const F3 nb = unpackn(q1.z);
            const F3 nc = unpackn(q1.w);

            const float b0 = bk[k][0], b1 = bk[k][1], b2 = bk[k][2];
            F3 pc, pn;
            pc.x = fmaf(b0, va.x, fmaf(b1, vb.x, b2 * vc.x));
            pc.y = fmaf(b0, va.y, fmaf(b1, vb.y, b2 * vc.y));
            pc.z = fmaf(b0, va.z, fmaf(b1, vb.z, b2 * vc.z));
            pn.x = fmaf(b0, na.x, fmaf(b1, nb.x, b2 * nc.x));
            pn.y = fmaf(b0, na.y, fmaf(b1, nb.y, b2 * nc.y));
            pn.z = fmaf(b0, na.z, fmaf(b1, nb.z, b2 * nc.z));

            // normals = normalize(pn) with max(norm,1e-6) semantics
            float inl = 1.0f / fmaxf(sqrtf(dot3(pn, pn)), 1e-6f);
            F3 nrm = { pn.x * inl, pn.y * inl, pn.z * inl };

            F3 dir = { Lloc.x - pc.x, Lloc.y - pc.y, Lloc.z - pc.z };
            float idl = 1.0f / fmaxf(sqrtf(dot3(dir, dir)), 1e-6f);
            dir.x *= idl; dir.y *= idl; dir.z *= idl;

            const float cosang = dot3(nrm, dir);
            const float rc = fmaxf(cosang, 0.0f);

            // reflect = 2*cos*n - dir
            F3 refl = { fmaf(2.0f * cosang, nrm.x, -dir.x),
                        fmaf(2.0f * cosang, nrm.y, -dir.y),
                        fmaf(2.0f * cosang, nrm.z, -dir.z) };

            F3 vw = { Cam.x - pc.x, Cam.y - pc.y, Cam.z - pc.z };
            float ivl = 1.0f / fmaxf(sqrtf(dot3(vw, vw)), 1e-6f);
            vw.x *= ivl; vw.y *= ivl; vw.z *= ivl;

            float sc = fmaxf(dot3(vw, refl), 0.0f);
            if (!(cosang > 0.0f)) sc = 0.0f;
            // sc^sh via MUFU lg2/ex2 pair; sc==0 -> 0 (sh > 0)
            const float spec = (sc > 0.0f) ? __powf(sc, sh) : 0.0f;

            // colors = (amb + kd*relu(cos)*vis) * texel + ks*spec
            col[k].x = fmaf(fmaf(kdv.x, rc, amb.x), tk[k][0], ks.x * spec);
            col[k].y = fmaf(fmaf(kdv.y, rc, amb.y), tk[k][1], ks.y * spec);
            col[k].z = fmaf(fmaf(kdv.z, rc, amb.z), tk[k][2], ks.z * spec);

            // prob = sigmoid(-dists/SIGMA) = 1/(1+exp(dists/SIGMA))
            prob[k] = __fdividef(1.0f, 1.0f + __expf(dsk[k] * INV_SIGMA));
            zinv[k] = (ZFAR_ - zbk[k]) * INV_ZRANGE;
        } else {
            col[k].x = col[k].y = col[k].z = 0.0f;
            prob[k] = 0.0f;
            zinv[k] = 0.0f;
        }
    }

    // ---- softmax blend ----
    float zmax = fmaxf(fmaxf(fmaxf(zinv[0], zinv[1]), fmaxf(zinv[2], zinv[3])),
                       EPS_BLEND_);

    float alpha = 1.0f - (1.0f - prob[0]) * (1.0f - prob[1])
                       * (1.0f - prob[2]) * (1.0f - prob[3]);

    float sumw = 0.0f;
    F3 acc = { 0.0f, 0.0f, 0.0f };
    #pragma unroll
    for (int k = 0; k < PK; k++) {
        const float w = prob[k] * __expf((zinv[k] - zmax) * INV_GAMMA);
        sumw += w;
        acc.x = fmaf(w, col[k].x, acc.x);
        acc.y = fmaf(w, col[k].y, acc.y);
        acc.z = fmaf(w, col[k].z, acc.z);
    }
    const float delta = __expf((EPS_BLEND_ - zmax) * INV_GAMMA);
    const float inv_denom = __fdividef(1.0f, sumw + delta);

    float4 o;
    o.x = (acc.x + delta) * inv_denom;   // BG = (1,1,1)
    o.y = (acc.y + delta) * inv_denom;
    o.z = (acc.z + delta) * inv_denom;
    o.w = alpha;
    ((float4*)out)[tid] = o;
}

extern "C" void kernel_launch(void* const* d_in, const int* in_sizes, int n_in,
                              void* d_out, int out_size) {
    const float* verts          = (const float*)d_in[0];
    const float* vnormals       = (const float*)d_in[1];
    const float* bary           = (const float*)d_in[2];
    const float* zbuf           = (const float*)d_in[3];
    const float* dists          = (const float*)d_in[4];
    const float* texels         = (const float*)d_in[5];
    const float* vis_maps       = (const float*)d_in[6];
    const float* light_location = (const float*)d_in[7];
    const float* light_ambient  = (const float*)d_in[8];
    const float* light_diffuse  = (const float*)d_in[9];
    const float* light_specular = (const float*)d_in[10];
    const float* camera_center  = (const float*)d_in[11];
    const float* mat_ambient    = (const float*)d_in[12];
    const float* mat_diffuse    = (const float*)d_in[13];
    const float* mat_specular   = (const float*)d_in[14];
    const float* shininess      = (const float*)d_in[15];
    const int*   faces          = (const int*)d_in[16];
    const int*   pix_to_face    = (const int*)d_in[17];

    // Pass 1: build packed per-face records (fp16 verts + 10-10-10 normals), 32B/face.
    build_face_records<<<(PF + 255) / 256, 256>>>(faces, verts, vnormals);

    // Pass 2: shade + blend.
    const int threads = 256;
    const int blocks  = (NPIX + threads - 1) / threads;
    soft_phong_kernel<<<blocks, threads>>>(
        bary, zbuf, dists, texels, vis_maps,
        light_location, light_ambient, light_diffuse, light_specular,
        camera_center, mat_ambient, mat_diffuse, mat_specular, shininess,
        pix_to_face, (float*)d_out);
}

// round 7
// speedup vs baseline: 1.3315x; 1.3315x over previous
#include <cuda_runtime.h>
#include <cuda_bf16.h>
#include <cuda_fp16.h>
#include <cstdint>

// Problem constants (fixed shapes for SoftPhongShaderShadow_36197984371119)
#define PN   8
#define PH   512
#define PW   512
#define PK   4
#define NPIX (PN * PH * PW)        // 2,097,152
#define HW_SHIFT 18                // H*W = 262144 = 2^18
#define PF   100000                // faces
#define PV   50000                 // verts

#define SIGMA_     1.0e-4f
#define GAMMA_     1.0e-4f
#define ZNEAR_     1.0f
#define ZFAR_      100.0f
#define EPS_BLEND_ 1e-10f
#define INV_SIGMA  (1.0f / SIGMA_)
#define INV_GAMMA  (1.0f / GAMMA_)
#define INV_ZRANGE (1.0f / (ZFAR_ - ZNEAR_))

struct F3 { float x, y, z; };

__device__ __forceinline__ F3 ldg3(const float* __restrict__ p) {
    F3 r; r.x = __ldg(p); r.y = __ldg(p + 1); r.z = __ldg(p + 2); return r;
}
__device__ __forceinline__ float dot3(F3 a, F3 b) {
    return fmaf(a.x, b.x, fmaf(a.y, b.y, a.z * b.z));
}

// Packed per-face fp16 record in a 64B-aligned slot (4 x uint4; 3 used):
//  q0 (8 halves): v0x v0y v0z v1x v1y v1z v2x v2y
//  q1 (8 halves): v2z n0x n0y n0z n1x n1y n1z n2x
//  q2 (low word): n2y n2z
// 48B payload inside a 64B slot -> never crosses a 128B line; 2 L2 sectors.
__device__ uint4 g_face_rec[PF * 4];

__device__ __forceinline__ uint32_t pack_h2(float a, float b) {
    __half2 h = __halves2half2(__float2half_rn(a), __float2half_rn(b));
    return *reinterpret_cast<uint32_t*>(&h);
}
__device__ __forceinline__ float2 unp_h2(uint32_t u) {
    return __half22float2(*reinterpret_cast<__half2*>(&u));
}

__global__ void __launch_bounds__(256)
build_face_records(const int*   __restrict__ faces,
                   const float* __restrict__ verts,
                   const float* __restrict__ vnormals)
{
    const int f = blockIdx.x * blockDim.x + threadIdx.x;
    if (f >= PF) return;
    const int i0 = __ldg(faces + 3 * f + 0);
    const int i1 = __ldg(faces + 3 * f + 1);
    const int i2 = __ldg(faces + 3 * f + 2);
    const F3 v0 = ldg3(verts + 3 * i0);
    const F3 v1 = ldg3(verts + 3 * i1);
    const F3 v2 = ldg3(verts + 3 * i2);
    const F3 n0 = ldg3(vnormals + 3 * i0);
    const F3 n1 = ldg3(vnormals + 3 * i1);
    const F3 n2 = ldg3(vnormals + 3 * i2);
    uint4* r = g_face_rec + (size_t)f * 4;
    uint4 q0, q1;
    q0.x = pack_h2(v0.x, v0.y);
    q0.y = pack_h2(v0.z, v1.x);
    q0.z = pack_h2(v1.y, v1.z);
    q0.w = pack_h2(v2.x, v2.y);
    q1.x = pack_h2(v2.z, n0.x);
    q1.y = pack_h2(n0.y, n0.z);
    q1.z = pack_h2(n1.x, n1.y);
    q1.w = pack_h2(n1.z, n2.x);
    uint4 q2 = make_uint4(pack_h2(n2.y, n2.z), 0u, 0u, 0u);
    r[0] = q0;
    r[1] = q1;
    r[2] = q2;
}

__global__ void __launch_bounds__(256, 4)
soft_phong_kernel(
    const float* __restrict__ bary,            // (N,H,W,K,3)
    const float* __restrict__ zbuf,            // (N,H,W,K)
    const float* __restrict__ dists,           // (N,H,W,K)
    const float* __restrict__ texels,          // (N,H,W,K,3)
    const float* __restrict__ vis_maps,        // (N,H,W,3)
    const float* __restrict__ light_location,  // (N,3)
    const float* __restrict__ light_ambient,   // (N,3)
    const float* __restrict__ light_diffuse,   // (N,3)
    const float* __restrict__ light_specular,  // (N,3)
    const float* __restrict__ camera_center,   // (N,3)
    const float* __restrict__ mat_ambient,     // (N,3)
    const float* __restrict__ mat_diffuse,     // (N,3)
    const float* __restrict__ mat_specular,    // (N,3)
    const float* __restrict__ shininess,       // (N,)
    const int*   __restrict__ pix_to_face,     // (N,H,W,K)
    float*       __restrict__ out)             // (N,H,W,4)
{
    const int tid = blockIdx.x * blockDim.x + threadIdx.x;
    if (tid >= NPIX) return;
    const int n = tid >> HW_SHIFT;

    // ---- streaming per-pixel loads (vectorized, streaming cache hint) ----
    const int4   p2f = __ldcs((const int4*)pix_to_face + tid);
    const float4 zb  = __ldcs((const float4*)zbuf + tid);
    const float4 ds  = __ldcs((const float4*)dists + tid);

    const float4* bp = (const float4*)(bary + (size_t)tid * 12);
    const float4 bv0 = __ldcs(bp + 0);
    const float4 bv1 = __ldcs(bp + 1);
    const float4 bv2 = __ldcs(bp + 2);

    const float4* tp = (const float4*)(texels + (size_t)tid * 12);
    const float4 tv0 = __ldcs(tp + 0);
    const float4 tv1 = __ldcs(tp + 1);
    const float4 tv2 = __ldcs(tp + 2);

    F3 vis;
    {
        const float* vp = vis_maps + (size_t)tid * 3;
        vis.x = __ldcs(vp); vis.y = __ldcs(vp + 1); vis.z = __ldcs(vp + 2);
    }

    // ---- per-batch constants (uniform per block -> L1 broadcast) ----
    const F3 Lloc = ldg3(light_location + 3 * n);
    const F3 Cam  = ldg3(camera_center + 3 * n);
    const F3 lamb = ldg3(light_ambient + 3 * n);
    const F3 ldif = ldg3(light_diffuse + 3 * n);
    const F3 lspc = ldg3(light_specular + 3 * n);
    const F3 mamb = ldg3(mat_ambient + 3 * n);
    const F3 mdif = ldg3(mat_diffuse + 3 * n);
    const F3 mspc = ldg3(mat_specular + 3 * n);
    const float sh = __ldg(shininess + n);

    // precombined coefficients
    const F3 amb  = { mamb.x * lamb.x, mamb.y * lamb.y, mamb.z * lamb.z };
    const F3 ks   = { mspc.x * lspc.x, mspc.y * lspc.y, mspc.z * lspc.z };
    const F3 kdv  = { mdif.x * ldif.x * vis.x,
                      mdif.y * ldif.y * vis.y,
                      mdif.z * ldif.z * vis.z };

    const int   fidx[PK] = { p2f.x, p2f.y, p2f.z, p2f.w };
    const float zbk[PK]  = { zb.x, zb.y, zb.z, zb.w };
    const float dsk[PK]  = { ds.x, ds.y, ds.z, ds.w };
    const float bk[PK][3] = {
        { bv0.x, bv0.y, bv0.z }, { bv0.w, bv1.x, bv1.y },
        { bv1.z, bv1.w, bv2.x }, { bv2.y, bv2.z, bv2.w } };
    const float tk[PK][3] = {
        { tv0.x, tv0.y, tv0.z }, { tv0.w, tv1.x, tv1.y },
        { tv1.z, tv1.w, tv2.x }, { tv2.y, tv2.z, tv2.w } };

    // ---- zmax pre-pass (needs only zbuf + mask, no gathers) ----
    float zinv[PK];
    #pragma unroll
    for (int k = 0; k < PK; k++)
        zinv[k] = (fidx[k] >= 0) ? (ZFAR_ - zbk[k]) * INV_ZRANGE : 0.0f;
    const float zmax = fmaxf(fmaxf(fmaxf(fmaxf(zinv[0], zinv[1]),
                                         fmaxf(zinv[2], zinv[3])), EPS_BLEND_), EPS_BLEND_);

    // ---- one-pass shade + accumulate blend ----
    float sumw = 0.0f;
    float keep = 1.0f;                 // prod(1 - prob)
    F3 acc = { 0.0f, 0.0f, 0.0f };

    #pragma unroll
    for (int k = 0; k < PK; k++) {
        const int f = fidx[k];
        if (f >= 0) {
            // gather packed fp16 face record: 2 x LDG.128 + 1 x LDG.32
            const uint4* fr = g_face_rec + (size_t)f * 4;
            const uint4 q0 = __ldg(fr + 0);
            const uint4 q1 = __ldg(fr + 1);
            const uint32_t q2 = __ldg((const uint32_t*)(fr + 2));

            const float2 a0 = unp_h2(q0.x);  // v0x v0y
            const float2 a1 = unp_h2(q0.y);  // v0z v1x
            const float2 a2 = unp_h2(q0.z);  // v1y v1z
            const float2 a3 = unp_h2(q0.w);  // v2x v2y
            const float2 a4 = unp_h2(q1.x);  // v2z n0x
            const float2 a5 = unp_h2(q1.y);  // n0y n0z
            const float2 a6 = unp_h2(q1.z);  // n1x n1y
            const float2 a7 = unp_h2(q1.w);  // n1z n2x
            const float2 a8 = unp_h2(q2);    // n2y n2z

            const F3 va = { a0.x, a0.y, a1.x };
            const F3 vb = { a1.y, a2.x, a2.y };
            const F3 vc = { a3.x, a3.y, a4.x };
            const F3 na = { a4.y, a5.x, a5.y };
            const F3 nb = { a6.x, a6.y, a7.x };
            const F3 nc = { a7.y, a8.x, a8.y };

            const float b0 = bk[k][0], b1 = bk[k][1], b2 = bk[k][2];
            F3 pc, pn;
            pc.x = fmaf(b0, va.x, fmaf(b1, vb.x, b2 * vc.x));
            pc.y = fmaf(b0, va.y, fmaf(b1, vb.y, b2 * vc.y));
            pc.z = fmaf(b0, va.z, fmaf(b1, vb.z, b2 * vc.z));
            pn.x = fmaf(b0, na.x, fmaf(b1, nb.x, b2 * nc.x));
            pn.y = fmaf(b0, na.y, fmaf(b1, nb.y, b2 * nc.y));
            pn.z = fmaf(b0, na.z, fmaf(b1, nb.z, b2 * nc.z));

            // normals = normalize(pn) with max(norm,1e-6) semantics
            float inl = 1.0f / fmaxf(sqrtf(dot3(pn, pn)), 1e-6f);
            F3 nrm = { pn.x * inl, pn.y * inl, pn.z * inl };

            F3 dir = { Lloc.x - pc.x, Lloc.y - pc.y, Lloc.z - pc.z };
            float idl = 1.0f / fmaxf(sqrtf(dot3(dir, dir)), 1e-6f);
            dir.x *= idl; dir.y *= idl; dir.z *= idl;

            const float cosang = dot3(nrm, dir);
            const float rc = fmaxf(cosang, 0.0f);

            // reflect = 2*cos*n - dir
            F3 refl = { fmaf(2.0f * cosang, nrm.x, -dir.x),
                        fmaf(2.0f * cosang, nrm.y, -dir.y),
                        fmaf(2.0f * cosang, nrm.z, -dir.z) };

            F3 vw = { Cam.x - pc.x, Cam.y - pc.y, Cam.z - pc.z };
            float ivl = 1.0f / fmaxf(sqrtf(dot3(vw, vw)), 1e-6f);
            vw.x *= ivl; vw.y *= ivl; vw.z *= ivl;

            float sc = fmaxf(dot3(vw, refl), 0.0f);
            if (!(cosang > 0.0f)) sc = 0.0f;
            // sc^sh via MUFU lg2/ex2 pair; sc==0 -> 0 (sh > 0)
            const float spec = (sc > 0.0f) ? __powf(sc, sh) : 0.0f;

            // colors = (amb + kd*relu(cos)*vis) * texel + ks*spec
            F3 col;
            col.x = fmaf(fmaf(kdv.x, rc, amb.x), tk[k][0], ks.x * spec);
            col.y = fmaf(fmaf(kdv.y, rc, amb.y), tk[k][1], ks.y * spec);
            col.z = fmaf(fmaf(kdv.z, rc, amb.z), tk[k][2], ks.z * spec);

            // prob = sigmoid(-dists/SIGMA) = 1/(1+exp(dists/SIGMA))
            const float p = __fdividef(1.0f, 1.0f + __expf(dsk[k] * INV_SIGMA));
            keep *= (1.0f - p);
            const float w = p * __expf((zinv[k] - zmax) * INV_GAMMA);
            sumw += w;
            acc.x = fmaf(w, col.x, acc.x);
            acc.y = fmaf(w, col.y, acc.y);
            acc.z = fmaf(w, col.z, acc.z);
        }
    }

    const float delta = __expf((EPS_BLEND_ - zmax) * INV_GAMMA);
    const float inv_denom = __fdividef(1.0f, sumw + delta);

    float4 o;
    o.x = (acc.x + delta) * inv_denom;   // BG = (1,1,1)
    o.y = (acc.y + delta) * inv_denom;
    o.z = (acc.z + delta) * inv_denom;
    o.w = 1.0f - keep;
    ((float4*)out)[tid] = o;
}

extern "C" void kernel_launch(void* const* d_in, const int* in_sizes, int n_in,
                              void* d_out, int out_size) {
    const float* verts          = (const float*)d_in[0];
    const float* vnormals       = (const float*)d_in[1];
    const float* bary           = (const float*)d_in[2];
    const float* zbuf           = (const float*)d_in[3];
    const float* dists          = (const float*)d_in[4];
    const float* texels         = (const float*)d_in[5];
    const float* vis_maps       = (const float*)d_in[6];
    const float* light_location = (const float*)d_in[7];
    const float* light_ambient  = (const float*)d_in[8];
    const float* light_diffuse  = (const float*)d_in[9];
    const float* light_specular = (const float*)d_in[10];
    const float* camera_center  = (const float*)d_in[11];
    const float* mat_ambient    = (const float*)d_in[12];
    const float* mat_diffuse    = (const float*)d_in[13];
    const float* mat_specular   = (const float*)d_in[14];
    const float* shininess      = (const float*)d_in[15];
    const int*   faces          = (const int*)d_in[16];
    const int*   pix_to_face    = (const int*)d_in[17];

    // Pass 1: build packed fp16 per-face records (verts+normals), 64B slot/face.
    build_face_records<<<(PF + 255) / 256, 256>>>(faces, verts, vnormals);

    // Pass 2: shade + blend.
    const int threads = 256;
    const int blocks  = (NPIX + threads - 1) / threads;
    soft_phong_kernel<<<blocks, threads>>>(
        bary, zbuf, dists, texels, vis_maps,
        light_location, light_ambient, light_diffuse, light_specular,
        camera_center, mat_ambient, mat_diffuse, mat_specular, shininess,
        pix_to_face, (float*)d_out);
}

// round 8
// speedup vs baseline: 1.4842x; 1.1147x over previous
#include <cuda_runtime.h>
#include <cuda_bf16.h>
#include <cuda_fp16.h>
#include <cstdint>

// Problem constants (fixed shapes for SoftPhongShaderShadow_36197984371119)
#define PN   8
#define PH   512
#define PW   512
#define PK   4
#define NPIX (PN * PH * PW)        // 2,097,152
#define HW_SHIFT 18                // H*W = 262144 = 2^18
#define PF   100000                // faces
#define PV   50000                 // verts

#define SIGMA_     1.0e-4f
#define GAMMA_     1.0e-4f
#define ZNEAR_     1.0f
#define ZFAR_      100.0f
#define EPS_BLEND_ 1e-10f
#define INV_SIGMA  (1.0f / SIGMA_)
#define INV_GAMMA  (1.0f / GAMMA_)
#define INV_ZRANGE (1.0f / (ZFAR_ - ZNEAR_))

struct F3 { float x, y, z; };

__device__ __forceinline__ F3 ldg3(const float* __restrict__ p) {
    F3 r; r.x = __ldg(p); r.y = __ldg(p + 1); r.z = __ldg(p + 2); return r;
}
__device__ __forceinline__ float dot3(F3 a, F3 b) {
    return fmaf(a.x, b.x, fmaf(a.y, b.y, a.z * b.z));
}

// Packed per-face fp16 record in a 64B-aligned slot (4 x uint4; 3 used):
//  q0 (8 halves): v0x v0y v0z v1x v1y v1z v2x v2y
//  q1 (8 halves): v2z n0x n0y n0z n1x n1y n1z n2x
//  q2 (low word): n2y n2z
// 48B payload inside a 64B slot -> never crosses a 128B line; 2 L2 sectors.
__device__ uint4 g_face_rec[PF * 4];

__device__ __forceinline__ uint32_t pack_h2(float a, float b) {
    __half2 h = __halves2half2(__float2half_rn(a), __float2half_rn(b));
    return *reinterpret_cast<uint32_t*>(&h);
}
__device__ __forceinline__ float2 unp_h2(uint32_t u) {
    return __half22float2(*reinterpret_cast<__half2*>(&u));
}

__global__ void __launch_bounds__(256)
build_face_records(const int*   __restrict__ faces,
                   const float* __restrict__ verts,
                   const float* __restrict__ vnormals)
{
    const int f = blockIdx.x * blockDim.x + threadIdx.x;
    if (f >= PF) return;
    const int i0 = __ldg(faces + 3 * f + 0);
    const int i1 = __ldg(faces + 3 * f + 1);
    const int i2 = __ldg(faces + 3 * f + 2);
    const F3 v0 = ldg3(verts + 3 * i0);
    const F3 v1 = ldg3(verts + 3 * i1);
    const F3 v2 = ldg3(verts + 3 * i2);
    const F3 n0 = ldg3(vnormals + 3 * i0);
    const F3 n1 = ldg3(vnormals + 3 * i1);
    const F3 n2 = ldg3(vnormals + 3 * i2);
    uint4* r = g_face_rec + (size_t)f * 4;
    uint4 q0, q1;
    q0.x = pack_h2(v0.x, v0.y);
    q0.y = pack_h2(v0.z, v1.x);
    q0.z = pack_h2(v1.y, v1.z);
    q0.w = pack_h2(v2.x, v2.y);
    q1.x = pack_h2(v2.z, n0.x);
    q1.y = pack_h2(n0.y, n0.z);
    q1.z = pack_h2(n1.x, n1.y);
    q1.w = pack_h2(n1.z, n2.x);
    uint4 q2 = make_uint4(pack_h2(n2.y, n2.z), 0u, 0u, 0u);
    r[0] = q0;
    r[1] = q1;
    r[2] = q2;
}

__global__ void __launch_bounds__(256)
soft_phong_kernel(
    const float* __restrict__ bary,            // (N,H,W,K,3)
    const float* __restrict__ zbuf,            // (N,H,W,K)
    const float* __restrict__ dists,           // (N,H,W,K)
    const float* __restrict__ texels,          // (N,H,W,K,3)
    const float* __restrict__ vis_maps,        // (N,H,W,3)
    const float* __restrict__ light_location,  // (N,3)
    const float* __restrict__ light_ambient,   // (N,3)
    const float* __restrict__ light_diffuse,   // (N,3)
    const float* __restrict__ light_specular,  // (N,3)
    const float* __restrict__ camera_center,   // (N,3)
    const float* __restrict__ mat_ambient,     // (N,3)
    const float* __restrict__ mat_diffuse,     // (N,3)
    const float* __restrict__ mat_specular,    // (N,3)
    const float* __restrict__ shininess,       // (N,)
    const int*   __restrict__ pix_to_face,     // (N,H,W,K)
    float*       __restrict__ out)             // (N,H,W,4)
{
    const int tid = blockIdx.x * blockDim.x + threadIdx.x;
    if (tid >= NPIX) return;
    const int n = tid >> HW_SHIFT;

    // ---- streaming per-pixel loads (vectorized, streaming cache hint) ----
    const int4   p2f = __ldcs((const int4*)pix_to_face + tid);
    const float4 zb  = __ldcs((const float4*)zbuf + tid);
    const float4 ds  = __ldcs((const float4*)dists + tid);

    const float4* bp = (const float4*)(bary + (size_t)tid * 12);
    const float4 bv0 = __ldcs(bp + 0);
    const float4 bv1 = __ldcs(bp + 1);
    const float4 bv2 = __ldcs(bp + 2);

    const float4* tp = (const float4*)(texels + (size_t)tid * 12);
    const float4 tv0 = __ldcs(tp + 0);
    const float4 tv1 = __ldcs(tp + 1);
    const float4 tv2 = __ldcs(tp + 2);

    F3 vis;
    {
        const float* vp = vis_maps + (size_t)tid * 3;
        vis.x = __ldcs(vp); vis.y = __ldcs(vp + 1); vis.z = __ldcs(vp + 2);
    }

    // ---- per-batch constants (uniform per block -> L1 broadcast) ----
    const F3 Lloc = ldg3(light_location + 3 * n);
    const F3 Cam  = ldg3(camera_center + 3 * n);
    const F3 lamb = ldg3(light_ambient + 3 * n);
    const F3 ldif = ldg3(light_diffuse + 3 * n);
    const F3 lspc = ldg3(light_specular + 3 * n);
    const F3 mamb = ldg3(mat_ambient + 3 * n);
    const F3 mdif = ldg3(mat_diffuse + 3 * n);
    const F3 mspc = ldg3(mat_specular + 3 * n);
    const float sh = __ldg(shininess + n);

    // precombined coefficients
    const F3 amb  = { mamb.x * lamb.x, mamb.y * lamb.y, mamb.z * lamb.z };
    const F3 ks   = { mspc.x * lspc.x, mspc.y * lspc.y, mspc.z * lspc.z };
    const F3 kdv  = { mdif.x * ldif.x * vis.x,
                      mdif.y * ldif.y * vis.y,
                      mdif.z * ldif.z * vis.z };

    const int   fidx[PK] = { p2f.x, p2f.y, p2f.z, p2f.w };
    const float zbk[PK]  = { zb.x, zb.y, zb.z, zb.w };
    const float dsk[PK]  = { ds.x, ds.y, ds.z, ds.w };
    const float bk[PK][3] = {
        { bv0.x, bv0.y, bv0.z }, { bv0.w, bv1.x, bv1.y },
        { bv1.z, bv1.w, bv2.x }, { bv2.y, bv2.z, bv2.w } };
    const float tk[PK][3] = {
        { tv0.x, tv0.y, tv0.z }, { tv0.w, tv1.x, tv1.y },
        { tv1.z, tv1.w, tv2.x }, { tv2.y, tv2.z, tv2.w } };

    // ---- blend weights from streaming data only (no gathers needed) ----
    float zinv[PK], prob[PK], w[PK];
    #pragma unroll
    for (int k = 0; k < PK; k++) {
        const bool valid = (fidx[k] >= 0);
        zinv[k] = valid ? (ZFAR_ - zbk[k]) * INV_ZRANGE : 0.0f;
        // prob = sigmoid(-dists/SIGMA) = 1/(1+exp(dists/SIGMA))
        prob[k] = valid ? __fdividef(1.0f, 1.0f + __expf(dsk[k] * INV_SIGMA)) : 0.0f;
    }
    const float zmax = fmaxf(fmaxf(fmaxf(zinv[0], zinv[1]),
                                   fmaxf(zinv[2], zinv[3])), EPS_BLEND_);
    #pragma unroll
    for (int k = 0; k < PK; k++)
        w[k] = prob[k] * __expf((zinv[k] - zmax) * INV_GAMMA);
    // (for non-max fragments the exp underflows to exactly 0 -> no contribution)

    const float alpha = 1.0f - (1.0f - prob[0]) * (1.0f - prob[1])
                             * (1.0f - prob[2]) * (1.0f - prob[3]);
    const float sumw = (w[0] + w[1]) + (w[2] + w[3]);

    // ---- shade ONLY fragments with nonzero blend weight (exact skip) ----
    F3 acc = { 0.0f, 0.0f, 0.0f };
    #pragma unroll
    for (int k = 0; k < PK; k++) {
        if (w[k] > 0.0f) {
            const int f = fidx[k];
            // gather packed fp16 face record: 2 x LDG.128 + 1 x LDG.32
            const uint4* fr = g_face_rec + (size_t)f * 4;
            const uint4 q0 = __ldg(fr + 0);
            const uint4 q1 = __ldg(fr + 1);
            const uint32_t q2 = __ldg((const uint32_t*)(fr + 2));

            const float2 a0 = unp_h2(q0.x);  // v0x v0y
            const float2 a1 = unp_h2(q0.y);  // v0z v1x
            const float2 a2 = unp_h2(q0.z);  // v1y v1z
            const float2 a3 = unp_h2(q0.w);  // v2x v2y
            const float2 a4 = unp_h2(q1.x);  // v2z n0x
            const float2 a5 = unp_h2(q1.y);  // n0y n0z
            const float2 a6 = unp_h2(q1.z);  // n1x n1y
            const float2 a7 = unp_h2(q1.w);  // n1z n2x
            const float2 a8 = unp_h2(q2);    // n2y n2z

            const F3 va = { a0.x, a0.y, a1.x };
            const F3 vb = { a1.y, a2.x, a2.y };
            const F3 vc = { a3.x, a3.y, a4.x };
            const F3 na = { a4.y, a5.x, a5.y };
            const F3 nb = { a6.x, a6.y, a7.x };
            const F3 nc = { a7.y, a8.x, a8.y };

            const float b0 = bk[k][0], b1 = bk[k][1], b2 = bk[k][2];
            F3 pc, pn;
            pc.x = fmaf(b0, va.x, fmaf(b1, vb.x, b2 * vc.x));
            pc.y = fmaf(b0, va.y, fmaf(b1, vb.y, b2 * vc.y));
            pc.z = fmaf(b0, va.z, fmaf(b1, vb.z, b2 * vc.z));
            pn.x = fmaf(b0, na.x, fmaf(b1, nb.x, b2 * nc.x));
            pn.y = fmaf(b0, na.y, fmaf(b1, nb.y, b2 * nc.y));
            pn.z = fmaf(b0, na.z, fmaf(b1, nb.z, b2 * nc.z));

            // normals = normalize(pn) with max(norm,1e-6) semantics
            float inl = 1.0f / fmaxf(sqrtf(dot3(pn, pn)), 1e-6f);
            F3 nrm = { pn.x * inl, pn.y * inl, pn.z * inl };

            F3 dir = { Lloc.x - pc.x, Lloc.y - pc.y, Lloc.z - pc.z };
            float idl = 1.0f / fmaxf(sqrtf(dot3(dir, dir)), 1e-6f);
            dir.x *= idl; dir.y *= idl; dir.z *= idl;

            const float cosang = dot3(nrm, dir);
            const float rc = fmaxf(cosang, 0.0f);

            // reflect = 2*cos*n - dir
            F3 refl = { fmaf(2.0f * cosang, nrm.x, -dir.x),
                        fmaf(2.0f * cosang, nrm.y, -dir.y),
                        fmaf(2.0f * cosang, nrm.z, -dir.z) };

            F3 vw = { Cam.x - pc.x, Cam.y - pc.y, Cam.z - pc.z };
            float ivl = 1.0f / fmaxf(sqrtf(dot3(vw, vw)), 1e-6f);
            vw.x *= ivl; vw.y *= ivl; vw.z *= ivl;

            float sc = fmaxf(dot3(vw, refl), 0.0f);
            if (!(cosang > 0.0f)) sc = 0.0f;
            // sc^sh via MUFU lg2/ex2 pair; sc==0 -> 0 (sh > 0)
            const float spec = (sc > 0.0f) ? __powf(sc, sh) : 0.0f;

            // colors = (amb + kd*relu(cos)*vis) * texel + ks*spec
            const float wx = w[k];
            acc.x = fmaf(wx, fmaf(fmaf(kdv.x, rc, amb.x), tk[k][0], ks.x * spec), acc.x);
            acc.y = fmaf(wx, fmaf(fmaf(kdv.y, rc, amb.y), tk[k][1], ks.y * spec), acc.y);
            acc.z = fmaf(wx, fmaf(fmaf(kdv.z, rc, amb.z), tk[k][2], ks.z * spec), acc.z);
        }
    }

    const float delta = __expf((EPS_BLEND_ - zmax) * INV_GAMMA);
    const float inv_denom = __fdividef(1.0f, sumw + delta);

    float4 o;
    o.x = (acc.x + delta) * inv_denom;   // BG = (1,1,1)
    o.y = (acc.y + delta) * inv_denom;
    o.z = (acc.z + delta) * inv_denom;
    o.w = alpha;
    ((float4*)out)[tid] = o;
}

extern "C" void kernel_launch(void* const* d_in, const int* in_sizes, int n_in,
                              void* d_out, int out_size) {
    const float* verts          = (const float*)d_in[0];
    const float* vnormals       = (const float*)d_in[1];
    const float* bary           = (const float*)d_in[2];
    const float* zbuf           = (const float*)d_in[3];
    const float* dists          = (const float*)d_in[4];
    const float* texels         = (const float*)d_in[5];
    const float* vis_maps       = (const float*)d_in[6];
    const float* light_location = (const float*)d_in[7];
    const float* light_ambient  = (const float*)d_in[8];
    const float* light_diffuse  = (const float*)d_in[9];
    const float* light_specular = (const float*)d_in[10];
    const float* camera_center  = (const float*)d_in[11];
    const float* mat_ambient    = (const float*)d_in[12];
    const float* mat_diffuse    = (const float*)d_in[13];
    const float* mat_specular   = (const float*)d_in[14];
    const float* shininess      = (const float*)d_in[15];
    const int*   faces          = (const int*)d_in[16];
    const int*   pix_to_face    = (const int*)d_in[17];

    // Pass 1: build packed fp16 per-face records (verts+normals), 64B slot/face.
    build_face_records<<<(PF + 255) / 256, 256>>>(faces, verts, vnormals);

    // Pass 2: shade + blend (only fragments with nonzero blend weight gather).
    const int threads = 256;
    const int blocks  = (NPIX + threads - 1) / threads;
    soft_phong_kernel<<<blocks, threads>>>(
        bary, zbuf, dists, texels, vis_maps,
        light_location, light_ambient, light_diffuse, light_specular,
        camera_center, mat_ambient, mat_diffuse, mat_specular, shininess,
        pix_to_face, (float*)d_out);
}

// round 11
// speedup vs baseline: 1.8727x; 1.2617x over previous
#include <cuda_runtime.h>
#include <cuda_bf16.h>
#include <cuda_fp16.h>
#include <cstdint>

// Problem constants (fixed shapes for SoftPhongShaderShadow_36197984371119)
#define PN   8
#define PH   512
#define PW   512
#define PK   4
#define NPIX (PN * PH * PW)        // 2,097,152
#define HW_SHIFT 18                // H*W = 262144 = 2^18
#define PF   100000                // faces
#define PV   50000                 // verts

#define SIGMA_     1.0e-4f
#define GAMMA_     1.0e-4f
#define ZNEAR_     1.0f
#define ZFAR_      100.0f
#define EPS_BLEND_ 1e-10f
#define INV_SIGMA  (1.0f / SIGMA_)
#define INV_GAMMA  (1.0f / GAMMA_)
#define INV_ZRANGE (1.0f / (ZFAR_ - ZNEAR_))

struct F3 { float x, y, z; };

__device__ __forceinline__ F3 ldg3(const float* __restrict__ p) {
    F3 r; r.x = __ldg(p); r.y = __ldg(p + 1); r.z = __ldg(p + 2); return r;
}
__device__ __forceinline__ float dot3(F3 a, F3 b) {
    return fmaf(a.x, b.x, fmaf(a.y, b.y, a.z * b.z));
}
// 4-way select with literal comparisons -> SEL chain, no local memory
__device__ __forceinline__ float sel4(int k, float a, float b, float c, float d) {
    float r = a;
    r = (k == 1) ? b : r;
    r = (k == 2) ? c : r;
    r = (k == 3) ? d : r;
    return r;
}
__device__ __forceinline__ int sel4i(int k, int a, int b, int c, int d) {
    int r = a;
    r = (k == 1) ? b : r;
    r = (k == 2) ? c : r;
    r = (k == 3) ? d : r;
    return r;
}

// Packed per-face fp16 record in a 64B-aligned slot (4 x uint4; 3 used):
//  q0 (8 halves): v0x v0y v0z v1x v1y v1z v2x v2y
//  q1 (8 halves): v2z n0x n0y n0z n1x n1y n1z n2x
//  q2 (low word): n2y n2z
__device__ uint4 g_face_rec[PF * 4];

__device__ __forceinline__ uint32_t pack_h2(float a, float b) {
    __half2 h = __halves2half2(__float2half_rn(a), __float2half_rn(b));
    return *reinterpret_cast<uint32_t*>(&h);
}
__device__ __forceinline__ float2 unp_h2(uint32_t u) {
    return __half22float2(*reinterpret_cast<__half2*>(&u));
}

__global__ void __launch_bounds__(256)
build_face_records(const int*   __restrict__ faces,
                   const float* __restrict__ verts,
                   const float* __restrict__ vnormals)
{
    const int f = blockIdx.x * blockDim.x + threadIdx.x;
    if (f >= PF) return;
    const int i0 = __ldg(faces + 3 * f + 0);
    const int i1 = __ldg(faces + 3 * f + 1);
    const int i2 = __ldg(faces + 3 * f + 2);
    const F3 v0 = ldg3(verts + 3 * i0);
    const F3 v1 = ldg3(verts + 3 * i1);
    const F3 v2 = ldg3(verts + 3 * i2);
    const F3 n0 = ldg3(vnormals + 3 * i0);
    const F3 n1 = ldg3(vnormals + 3 * i1);
    const F3 n2 = ldg3(vnormals + 3 * i2);
    uint4* r = g_face_rec + (size_t)f * 4;
    uint4 q0, q1;
    q0.x = pack_h2(v0.x, v0.y);
    q0.y = pack_h2(v0.z, v1.x);
    q0.z = pack_h2(v1.y, v1.z);
    q0.w = pack_h2(v2.x, v2.y);
    q1.x = pack_h2(v2.z, n0.x);
    q1.y = pack_h2(n0.y, n0.z);
    q1.z = pack_h2(n1.x, n1.y);
    q1.w = pack_h2(n1.z, n2.x);
    uint4 q2 = make_uint4(pack_h2(n2.y, n2.z), 0u, 0u, 0u);
    r[0] = q0;
    r[1] = q1;
    r[2] = q2;
}

__global__ void __launch_bounds__(256)
soft_phong_kernel(
    const float* __restrict__ bary,            // (N,H,W,K,3)
    const float* __restrict__ zbuf,            // (N,H,W,K)
    const float* __restrict__ dists,           // (N,H,W,K)
    const float* __restrict__ texels,          // (N,H,W,K,3)
    const float* __restrict__ vis_maps,        // (N,H,W,3)
    const float* __restrict__ light_location,  // (N,3)
    const float* __restrict__ light_ambient,   // (N,3)
    const float* __restrict__ light_diffuse,   // (N,3)
    const float* __restrict__ light_specular,  // (N,3)
    const float* __restrict__ camera_center,   // (N,3)
    const float* __restrict__ mat_ambient,     // (N,3)
    const float* __restrict__ mat_diffuse,     // (N,3)
    const float* __restrict__ mat_specular,    // (N,3)
    const float* __restrict__ shininess,       // (N,)
    const int*   __restrict__ pix_to_face,     // (N,H,W,K)
    float*       __restrict__ out)             // (N,H,W,4)
{
    const int tid = blockIdx.x * blockDim.x + threadIdx.x;
    if (tid >= NPIX) return;
    const int n = tid >> HW_SHIFT;

    // ---- streaming per-pixel loads (vectorized, streaming cache hint) ----
    const int4   p2f = __ldcs((const int4*)pix_to_face + tid);
    const float4 zb  = __ldcs((const float4*)zbuf + tid);
    const float4 ds  = __ldcs((const float4*)dists + tid);

    const float4* bp = (const float4*)(bary + (size_t)tid * 12);
    const float4 bv0 = __ldcs(bp + 0);
    const float4 bv1 = __ldcs(bp + 1);
    const float4 bv2 = __ldcs(bp + 2);

    const float4* tp = (const float4*)(texels + (size_t)tid * 12);
    const float4 tv0 = __ldcs(tp + 0);
    const float4 tv1 = __ldcs(tp + 1);
    const float4 tv2 = __ldcs(tp + 2);

    F3 vis;
    {
        const float* vp = vis_maps + (size_t)tid * 3;
        vis.x = __ldcs(vp); vis.y = __ldcs(vp + 1); vis.z = __ldcs(vp + 2);
    }

    // ---- per-batch constants (uniform per block -> L1 broadcast) ----
    const F3 Lloc = ldg3(light_location + 3 * n);
    const F3 Cam  = ldg3(camera_center + 3 * n);
    const F3 lamb = ldg3(light_ambient + 3 * n);
    const F3 ldif = ldg3(light_diffuse + 3 * n);
    const F3 lspc = ldg3(light_specular + 3 * n);
    const F3 mamb = ldg3(mat_ambient + 3 * n);
    const F3 mdif = ldg3(mat_diffuse + 3 * n);
    const F3 mspc = ldg3(mat_specular + 3 * n);
    const float sh = __ldg(shininess + n);

    // precombined coefficients
    const F3 amb  = { mamb.x * lamb.x, mamb.y * lamb.y, mamb.z * lamb.z };
    const F3 ks   = { mspc.x * lspc.x, mspc.y * lspc.y, mspc.z * lspc.z };
    const F3 kdv  = { mdif.x * ldif.x * vis.x,
                      mdif.y * ldif.y * vis.y,
                      mdif.z * ldif.z * vis.z };

    // ---- blend weights from streaming data only (no gathers needed) ----
    float zinv[PK], prob[PK], w[PK];
    {
        const int   fi[PK] = { p2f.x, p2f.y, p2f.z, p2f.w };
        const float zk[PK] = { zb.x, zb.y, zb.z, zb.w };
        const float dk[PK] = { ds.x, ds.y, ds.z, ds.w };
        #pragma unroll
        for (int k = 0; k < PK; k++) {
            const bool valid = (fi[k] >= 0);
            zinv[k] = valid ? (ZFAR_ - zk[k]) * INV_ZRANGE : 0.0f;
            prob[k] = valid ? __fdividef(1.0f, 1.0f + __expf(dk[k] * INV_SIGMA)) : 0.0f;
        }
    }
    const float zmax = fmaxf(fmaxf(fmaxf(zinv[0], zinv[1]),
                                   fmaxf(zinv[2], zinv[3])), EPS_BLEND_);
    #pragma unroll
    for (int k = 0; k < PK; k++)
        w[k] = prob[k] * __expf((zinv[k] - zmax) * INV_GAMMA);
    // exp underflows to exactly 0 for non-contending fragments -> exact skip

    const float alpha = 1.0f - (1.0f - prob[0]) * (1.0f - prob[1])
                             * (1.0f - prob[2]) * (1.0f - prob[3]);
    const float sumw = (w[0] + w[1]) + (w[2] + w[3]);

    // survivor bitmask (typically exactly one bit set)
    unsigned mask = (w[0] > 0.0f ? 1u : 0u) | (w[1] > 0.0f ? 2u : 0u)
                  | (w[2] > 0.0f ? 4u : 0u) | (w[3] > 0.0f ? 8u : 0u);

    // ---- dense survivor loop: ~1 warp-iteration typical ----
    F3 acc = { 0.0f, 0.0f, 0.0f };
    while (mask) {
        const int k = __ffs(mask) - 1;
        mask &= mask - 1u;

        const int f = sel4i(k, p2f.x, p2f.y, p2f.z, p2f.w);
        const float wk = sel4(k, w[0], w[1], w[2], w[3]);
        const float b0 = sel4(k, bv0.x, bv0.w, bv1.z, bv2.y);
        const float b1 = sel4(k, bv0.y, bv1.x, bv1.w, bv2.z);
        const float b2 = sel4(k, bv0.z, bv1.y, bv2.x, bv2.w);
        const float t0 = sel4(k, tv0.x, tv0.w, tv1.z, tv2.y);
        const float t1 = sel4(k, tv0.y, tv1.x, tv1.w, tv2.z);
        const float t2 = sel4(k, tv0.z, tv1.y, tv2.x, tv2.w);

        // gather packed fp16 face record: 2 x LDG.128 + 1 x LDG.32
        const uint4* fr = g_face_rec + (size_t)f * 4;
        const uint4 q0 = __ldg(fr + 0);
        const uint4 q1 = __ldg(fr + 1);
        const uint32_t q2 = __ldg((const uint32_t*)(fr + 2));

        const float2 a0 = unp_h2(q0.x);  // v0x v0y
        const float2 a1 = unp_h2(q0.y);  // v0z v1x
        const float2 a2 = unp_h2(q0.z);  // v1y v1z
        const float2 a3 = unp_h2(q0.w);  // v2x v2y
        const float2 a4 = unp_h2(q1.x);  // v2z n0x
        const float2 a5 = unp_h2(q1.y);  // n0y n0z
        const float2 a6 = unp_h2(q1.z);  // n1x n1y
        const float2 a7 = unp_h2(q1.w);  // n1z n2x
        const float2 a8 = unp_h2(q2);    // n2y n2z

        const F3 va = { a0.x, a0.y, a1.x };
        const F3 vb = { a1.y, a2.x, a2.y };
        const F3 vc = { a3.x, a3.y, a4.x };
        const F3 na = { a4.y, a5.x, a5.y };
        const F3 nb = { a6.x, a6.y, a7.x };
        const F3 nc = { a7.y, a8.x, a8.y };

        F3 pc, pn;
        pc.x = fmaf(b0, va.x, fmaf(b1, vb.x, b2 * vc.x));
        pc.y = fmaf(b0, va.y, fmaf(b1, vb.y, b2 * vc.y));
        pc.z = fmaf(b0, va.z, fmaf(b1, vb.z, b2 * vc.z));
        pn.x = fmaf(b0, na.x, fmaf(b1, nb.x, b2 * nc.x));
        pn.y = fmaf(b0, na.y, fmaf(b1, nb.y, b2 * nc.y));
        pn.z = fmaf(b0, na.z, fmaf(b1, nb.z, b2 * nc.z));

        // normals = normalize(pn) with max(norm,1e-6) semantics
        float inl = 1.0f / fmaxf(sqrtf(dot3(pn, pn)), 1e-6f);
        F3 nrm = { pn.x * inl, pn.y * inl, pn.z * inl };

        F3 dir = { Lloc.x - pc.x, Lloc.y - pc.y, Lloc.z - pc.z };
        float idl = 1.0f / fmaxf(sqrtf(dot3(dir, dir)), 1e-6f);
        dir.x *= idl; dir.y *= idl; dir.z *= idl;

        const float cosang = dot3(nrm, dir);
        const float rc = fmaxf(cosang, 0.0f);

        F3 refl = { fmaf(2.0f * cosang, nrm.x, -dir.x),
                    fmaf(2.0f * cosang, nrm.y, -dir.y),
                    fmaf(2.0f * cosang, nrm.z, -dir.z) };

        F3 vw = { Cam.x - pc.x, Cam.y - pc.y, Cam.z - pc.z };
        float ivl = 1.0f / fmaxf(sqrtf(dot3(vw, vw)), 1e-6f);
        vw.x *= ivl; vw.y *= ivl; vw.z *= ivl;

        float sc = fmaxf(dot3(vw, refl), 0.0f);
        if (!(cosang > 0.0f)) sc = 0.0f;
        const float spec = (sc > 0.0f) ? __powf(sc, sh) : 0.0f;

        acc.x = fmaf(wk, fmaf(fmaf(kdv.x, rc, amb.x), t0, ks.x * spec), acc.x);
        acc.y = fmaf(wk, fmaf(fmaf(kdv.y, rc, amb.y), t1, ks.y * spec), acc.y);
        acc.z = fmaf(wk, fmaf(fmaf(kdv.z, rc, amb.z), t2, ks.z * spec), acc.z);
    }

    const float delta = __expf((EPS_BLEND_ - zmax) * INV_GAMMA);
    const float inv_denom = __fdividef(1.0f, sumw + delta);

    float4 o;
    o.x = (acc.x + delta) * inv_denom;   // BG = (1,1,1)
    o.y = (acc.y + delta) * inv_denom;
    o.z = (acc.z + delta) * inv_denom;
    o.w = alpha;
    ((float4*)out)[tid] = o;
}

extern "C" void kernel_launch(void* const* d_in, const int* in_sizes, int n_in,
                              void* d_out, int out_size) {
    const float* verts          = (const float*)d_in[0];
    const float* vnormals       = (const float*)d_in[1];
    const float* bary           = (const float*)d_in[2];
    const float* zbuf           = (const float*)d_in[3];
    const float* dists          = (const float*)d_in[4];
    const float* texels         = (const float*)d_in[5];
    const float* vis_maps       = (const float*)d_in[6];
    const float* light_location = (const float*)d_in[7];
    const float* light_ambient  = (const float*)d_in[8];
    const float* light_diffuse  = (const float*)d_in[9];
    const float* light_specular = (const float*)d_in[10];
    const float* camera_center  = (const float*)d_in[11];
    const float* mat_ambient    = (const float*)d_in[12];
    const float* mat_diffuse    = (const float*)d_in[13];
    const float* mat_specular   = (const float*)d_in[14];
    const float* shininess      = (const float*)d_in[15];
    const int*   faces          = (const int*)d_in[16];
    const int*   pix_to_face    = (const int*)d_in[17];

    // Pass 1: build packed fp16 per-face records (verts+normals), 64B slot/face.
    build_face_records<<<(PF + 255) / 256, 256>>>(faces, verts, vnormals);

    // Pass 2: shade + blend (dense survivor loop).
    const int threads = 256;
    const int blocks  = (NPIX + threads - 1) / threads;
    soft_phong_kernel<<<blocks, threads>>>(
        bary, zbuf, dists, texels, vis_maps,
        light_location, light_ambient, light_diffuse, light_specular,
        camera_center, mat_ambient, mat_diffuse, mat_specular, shininess,
        pix_to_face, (float*)d_out);
}